// round 3
// baseline (speedup 1.0000x reference)
#include <cuda_runtime.h>
#include <math.h>

// Problem constants
#define NB 2
#define T 2048
#define DM 1024
#define NH 16
#define DK 64
#define NT (NB*T)           // 4096 rows

// Scratch (device globals — no allocations allowed)
__device__ float g_Qh[NB*NH*T*DK];
__device__ float g_Kh[NB*NH*T*DK];
__device__ float g_Vh[NB*NH*T*DK];
__device__ float g_A [NT*DM];

// ---------------------------------------------------------------------------
// GEMM: C[M,N] = A[M,K] @ B[K,N] + bias[N]
// mode 0: row-major out. mode 1: head-split scatter out[((b*NH+h)*T+t)*DK+d]
// 128x128 block tile, TK=8, 256 threads, 8x8 micro-tile.
// ---------------------------------------------------------------------------
__global__ __launch_bounds__(256) void gemm_kernel(
    const float* __restrict__ A, const float* __restrict__ B,
    const float* __restrict__ bias, float* __restrict__ C,
    int M, int N, int K, int mode)
{
    __shared__ float As[8][128];
    __shared__ float Bs[8][128];

    int tid = threadIdx.x;
    int bm = blockIdx.y * 128;
    int bn = blockIdx.x * 128;
    int tx = tid & 15;
    int ty = tid >> 4;

    float acc[8][8];
#pragma unroll
    for (int i = 0; i < 8; i++)
#pragma unroll
        for (int j = 0; j < 8; j++) acc[i][j] = 0.f;

    int a_m = tid >> 1;
    int a_k = (tid & 1) * 4;
    int b_k = tid >> 5;
    int b_n = (tid & 31) * 4;

    for (int k0 = 0; k0 < K; k0 += 8) {
        float4 av = *(const float4*)&A[(size_t)(bm + a_m) * K + k0 + a_k];
        As[a_k + 0][a_m] = av.x;
        As[a_k + 1][a_m] = av.y;
        As[a_k + 2][a_m] = av.z;
        As[a_k + 3][a_m] = av.w;
        float4 bv = *(const float4*)&B[(size_t)(k0 + b_k) * N + bn + b_n];
        *(float4*)&Bs[b_k][b_n] = bv;
        __syncthreads();
#pragma unroll
        for (int kk = 0; kk < 8; kk++) {
            float a[8], b[8];
            *(float4*)&a[0] = *(const float4*)&As[kk][ty * 4];
            *(float4*)&a[4] = *(const float4*)&As[kk][64 + ty * 4];
            *(float4*)&b[0] = *(const float4*)&Bs[kk][tx * 4];
            *(float4*)&b[4] = *(const float4*)&Bs[kk][64 + tx * 4];
#pragma unroll
            for (int i = 0; i < 8; i++)
#pragma unroll
                for (int j = 0; j < 8; j++)
                    acc[i][j] += a[i] * b[j];
        }
        __syncthreads();
    }

#pragma unroll
    for (int i = 0; i < 8; i++) {
        int m = bm + ty * 4 + (i & 3) + (i & 4) * 16;
#pragma unroll
        for (int j = 0; j < 8; j++) {
            int n = bn + tx * 4 + (j & 3) + (j & 4) * 16;
            float v = acc[i][j] + bias[n];
            if (mode == 0) {
                C[(size_t)m * N + n] = v;
            } else {
                int bb = m >> 11;        // /T
                int t  = m & (T - 1);
                int h  = n >> 6;         // /DK
                int d  = n & (DK - 1);
                C[(((size_t)(bb * NH + h)) * T + t) * DK + d] = v;
            }
        }
    }
}

// ---------------------------------------------------------------------------
// Flash attention: per (q-tile 64, head, batch). 256 threads.
// Qt/Kt transposed [d][r] stride 68, Vs [c][d] stride 68, Ps [r][c] stride 68.
// Each thread: 4 q-rows (ty*4+i) x 4 cols (tx*4+j).
// ---------------------------------------------------------------------------
#define BQ 64
#define BK 64
#define SST 68
#define ATTN_SMEM (4 * BQ * SST * 4)

__global__ __launch_bounds__(256) void attn_kernel(
    const float* __restrict__ Qh, const float* __restrict__ Kh,
    const float* __restrict__ Vh, const int* __restrict__ mask,
    float* __restrict__ Aout)
{
    extern __shared__ float sm[];
    float* Qt = sm;                 // [64 d][68]
    float* Kt = Qt + BQ * SST;      // [64 d][68]
    float* Vs = Kt + BK * SST;      // [64 c][68]
    float* Ps = Vs + BK * SST;      // [64 r][68]
    __shared__ float Mk[BK];

    int tid = threadIdx.x;
    int tx = tid & 15;
    int ty = tid >> 4;
    int q0 = blockIdx.x * BQ;
    int h  = blockIdx.y;
    int b  = blockIdx.z;
    int bh = b * NH + h;

    const float* Qbase = Qh + ((size_t)bh * T + q0) * DK;
    const float* Kbase = Kh + (size_t)bh * T * DK;
    const float* Vbase = Vh + (size_t)bh * T * DK;

    // Load Q tile transposed
    for (int i = tid; i < BQ * 16; i += 256) {
        int r  = i >> 4;
        int d4 = (i & 15) * 4;
        float4 qv = *(const float4*)&Qbase[r * DK + d4];
        Qt[(d4 + 0) * SST + r] = qv.x;
        Qt[(d4 + 1) * SST + r] = qv.y;
        Qt[(d4 + 2) * SST + r] = qv.z;
        Qt[(d4 + 3) * SST + r] = qv.w;
    }

    float m_r[4], l_r[4], acc[4][4];
#pragma unroll
    for (int i = 0; i < 4; i++) {
        m_r[i] = -1e30f;
        l_r[i] = 0.f;
#pragma unroll
        for (int j = 0; j < 4; j++) acc[i][j] = 0.f;
    }

    const float scale = 0.125f;   // 1/sqrt(64)

    for (int k0 = 0; k0 < T; k0 += BK) {
        // Load K (transposed) and V tiles + mask
        for (int i = tid; i < BK * 16; i += 256) {
            int r  = i >> 4;
            int d4 = (i & 15) * 4;
            float4 kv = *(const float4*)&Kbase[(k0 + r) * DK + d4];
            Kt[(d4 + 0) * SST + r] = kv.x;
            Kt[(d4 + 1) * SST + r] = kv.y;
            Kt[(d4 + 2) * SST + r] = kv.z;
            Kt[(d4 + 3) * SST + r] = kv.w;
            float4 vv = *(const float4*)&Vbase[(k0 + r) * DK + d4];
            *(float4*)&Vs[r * SST + d4] = vv;
        }
        if (tid < BK)
            Mk[tid] = mask[b * T + k0 + tid] ? 0.f : -1e30f;
        __syncthreads();

        // Scores: 4x4 per thread
        float s[4][4];
#pragma unroll
        for (int i = 0; i < 4; i++)
#pragma unroll
            for (int j = 0; j < 4; j++) s[i][j] = 0.f;

#pragma unroll 8
        for (int d = 0; d < DK; d++) {
            float4 a = *(const float4*)&Qt[d * SST + ty * 4];
            float4 bb = *(const float4*)&Kt[d * SST + tx * 4];
            s[0][0] += a.x * bb.x; s[0][1] += a.x * bb.y; s[0][2] += a.x * bb.z; s[0][3] += a.x * bb.w;
            s[1][0] += a.y * bb.x; s[1][1] += a.y * bb.y; s[1][2] += a.y * bb.z; s[1][3] += a.y * bb.w;
            s[2][0] += a.z * bb.x; s[2][1] += a.z * bb.y; s[2][2] += a.z * bb.z; s[2][3] += a.z * bb.w;
            s[3][0] += a.w * bb.x; s[3][1] += a.w * bb.y; s[3][2] += a.w * bb.z; s[3][3] += a.w * bb.w;
        }

        float mk0 = Mk[tx * 4 + 0], mk1 = Mk[tx * 4 + 1];
        float mk2 = Mk[tx * 4 + 2], mk3 = Mk[tx * 4 + 3];

#pragma unroll
        for (int i = 0; i < 4; i++) {
            float sc0 = s[i][0] * scale + mk0;
            float sc1 = s[i][1] * scale + mk1;
            float sc2 = s[i][2] * scale + mk2;
            float sc3 = s[i][3] * scale + mk3;
            float mx = fmaxf(fmaxf(sc0, sc1), fmaxf(sc2, sc3));
#pragma unroll
            for (int msk = 8; msk >= 1; msk >>= 1)
                mx = fmaxf(mx, __shfl_xor_sync(0xffffffffu, mx, msk));
            float m_new = fmaxf(m_r[i], mx);
            float p0 = __expf(sc0 - m_new);
            float p1 = __expf(sc1 - m_new);
            float p2 = __expf(sc2 - m_new);
            float p3 = __expf(sc3 - m_new);
            float sum = p0 + p1 + p2 + p3;
#pragma unroll
            for (int msk = 8; msk >= 1; msk >>= 1)
                sum += __shfl_xor_sync(0xffffffffu, sum, msk);
            float alpha = __expf(m_r[i] - m_new);
            l_r[i] = l_r[i] * alpha + sum;
            m_r[i] = m_new;
            acc[i][0] *= alpha; acc[i][1] *= alpha;
            acc[i][2] *= alpha; acc[i][3] *= alpha;
            int r = ty * 4 + i;
            Ps[r * SST + tx * 4 + 0] = p0;
            Ps[r * SST + tx * 4 + 1] = p1;
            Ps[r * SST + tx * 4 + 2] = p2;
            Ps[r * SST + tx * 4 + 3] = p3;
        }
        __syncthreads();

        // PV accumulation
#pragma unroll 4
        for (int c = 0; c < BK; c++) {
            float4 vv = *(const float4*)&Vs[c * SST + tx * 4];
#pragma unroll
            for (int i = 0; i < 4; i++) {
                float p = Ps[(ty * 4 + i) * SST + c];
                acc[i][0] += p * vv.x;
                acc[i][1] += p * vv.y;
                acc[i][2] += p * vv.z;
                acc[i][3] += p * vv.w;
            }
        }
        __syncthreads();
    }

    // Write A in [N*T, DM] layout
#pragma unroll
    for (int i = 0; i < 4; i++) {
        float inv = 1.f / l_r[i];
        int t = q0 + ty * 4 + i;
        float4 o;
        o.x = acc[i][0] * inv;
        o.y = acc[i][1] * inv;
        o.z = acc[i][2] * inv;
        o.w = acc[i][3] * inv;
        *(float4*)&Aout[((size_t)(b * T + t)) * DM + h * DK + tx * 4] = o;
    }
}

// ---------------------------------------------------------------------------
extern "C" void kernel_launch(void* const* d_in, const int* in_sizes, int n_in,
                              void* d_out, int out_size)
{
    const float* q   = (const float*)d_in[0];
    const float* k   = (const float*)d_in[1];
    const float* v   = (const float*)d_in[2];
    const int*   msk = (const int*)  d_in[3];
    const float* Wq  = (const float*)d_in[4];
    const float* bq  = (const float*)d_in[5];
    const float* Wk  = (const float*)d_in[6];
    const float* bk  = (const float*)d_in[7];
    const float* Wv  = (const float*)d_in[8];
    const float* bv  = (const float*)d_in[9];
    const float* Wo  = (const float*)d_in[10];
    const float* bo  = (const float*)d_in[11];
    float* out = (float*)d_out;

    float* Qh;  cudaGetSymbolAddress((void**)&Qh, g_Qh);
    float* Kh;  cudaGetSymbolAddress((void**)&Kh, g_Kh);
    float* Vh;  cudaGetSymbolAddress((void**)&Vh, g_Vh);
    float* Abuf; cudaGetSymbolAddress((void**)&Abuf, g_A);

    cudaFuncSetAttribute(attn_kernel,
                         cudaFuncAttributeMaxDynamicSharedMemorySize, ATTN_SMEM);

    dim3 gg(DM / 128, NT / 128);   // (8, 32)
    gemm_kernel<<<gg, 256>>>(q, Wq, bq, Qh, NT, DM, DM, 1);
    gemm_kernel<<<gg, 256>>>(k, Wk, bk, Kh, NT, DM, DM, 1);
    gemm_kernel<<<gg, 256>>>(v, Wv, bv, Vh, NT, DM, DM, 1);

    dim3 ga(T / BQ, NH, NB);       // (32, 16, 2)
    attn_kernel<<<ga, 256, ATTN_SMEM>>>(Qh, Kh, Vh, msk, Abuf);

    gemm_kernel<<<gg, 256>>>(Abuf, Wo, bo, out, NT, DM, DM, 0);
}

// round 4
// speedup vs baseline: 1.1422x; 1.1422x over previous
#include <cuda_runtime.h>
#include <math.h>

// Problem constants
#define NB 2
#define T 2048
#define DM 1024
#define NH 16
#define DK 64
#define NT (NB*T)           // 4096 rows

typedef unsigned long long ull;

// ---- packed fp32x2 helpers (sm_100+ PTX) ----------------------------------
__device__ __forceinline__ ull pack2(float lo, float hi) {
    ull r; asm("mov.b64 %0, {%1, %2};" : "=l"(r) : "f"(lo), "f"(hi)); return r;
}
__device__ __forceinline__ ull dup2(float v) { return pack2(v, v); }
__device__ __forceinline__ void unpack2(ull v, float& lo, float& hi) {
    asm("mov.b64 {%0, %1}, %2;" : "=f"(lo), "=f"(hi) : "l"(v));
}
__device__ __forceinline__ void ffma2(ull& d, ull a, ull b) {
    asm("fma.rn.f32x2 %0, %1, %2, %0;" : "+l"(d) : "l"(a), "l"(b));
}
__device__ __forceinline__ ull mul2(ull a, ull b) {
    ull r; asm("mul.rn.f32x2 %0, %1, %2;" : "=l"(r) : "l"(a), "l"(b)); return r;
}

// Scratch (device globals — no allocations allowed)
__device__ float g_Qh[NB*NH*T*DK];
__device__ float g_Kh[NB*NH*T*DK];
__device__ float g_Vh[NB*NH*T*DK];
__device__ float g_A [NT*DM];

// ---------------------------------------------------------------------------
// GEMM: C[M,N] = A[M,K] @ B[K,N] + bias[N]
// mode 0: row-major out. mode 1: head-split scatter out[((b*NH+h)*T+t)*DK+d]
// 128x128 tile, TK=8, 256 threads, 8x8 micro-tile, f32x2 FMA, double-buffered.
// ---------------------------------------------------------------------------
__global__ __launch_bounds__(256) void gemm_kernel(
    const float* __restrict__ A, const float* __restrict__ B,
    const float* __restrict__ bias, float* __restrict__ C,
    int M, int N, int K, int mode)
{
    __shared__ float As[2][8][128];
    __shared__ float Bs[2][8][128];

    int tid = threadIdx.x;
    int bm = blockIdx.y * 128;
    int bn = blockIdx.x * 128;
    int tx = tid & 15;
    int ty = tid >> 4;

    ull acc2[8][4];
#pragma unroll
    for (int i = 0; i < 8; i++)
#pragma unroll
        for (int j = 0; j < 4; j++) acc2[i][j] = 0ULL;

    int a_m = tid >> 1;
    int a_k = (tid & 1) * 4;
    int b_k = tid >> 5;
    int b_n = (tid & 31) * 4;

    const float* Aptr = A + (size_t)(bm + a_m) * K + a_k;
    const float* Bptr = B + (size_t)b_k * N + bn + b_n;

    // preload tile 0
    float4 av = *(const float4*)Aptr;
    float4 bv = *(const float4*)Bptr;
    As[0][a_k + 0][a_m] = av.x;
    As[0][a_k + 1][a_m] = av.y;
    As[0][a_k + 2][a_m] = av.z;
    As[0][a_k + 3][a_m] = av.w;
    *(float4*)&Bs[0][b_k][b_n] = bv;
    __syncthreads();

    int p = 0;
    for (int k0 = 0; k0 < K; k0 += 8) {
        bool more = (k0 + 8 < K);
        if (more) {
            av = *(const float4*)(Aptr + k0 + 8);
            bv = *(const float4*)(Bptr + (size_t)(k0 + 8) * N);
        }
#pragma unroll
        for (int kk = 0; kk < 8; kk++) {
            float a[8];
            *(float4*)&a[0] = *(const float4*)&As[p][kk][ty * 4];
            *(float4*)&a[4] = *(const float4*)&As[p][kk][64 + ty * 4];
            ulonglong2 b01 = *(const ulonglong2*)&Bs[p][kk][tx * 4];
            ulonglong2 b23 = *(const ulonglong2*)&Bs[p][kk][64 + tx * 4];
#pragma unroll
            for (int i = 0; i < 8; i++) {
                ull ad = dup2(a[i]);
                ffma2(acc2[i][0], ad, b01.x);
                ffma2(acc2[i][1], ad, b01.y);
                ffma2(acc2[i][2], ad, b23.x);
                ffma2(acc2[i][3], ad, b23.y);
            }
        }
        if (more) {
            As[p ^ 1][a_k + 0][a_m] = av.x;
            As[p ^ 1][a_k + 1][a_m] = av.y;
            As[p ^ 1][a_k + 2][a_m] = av.z;
            As[p ^ 1][a_k + 3][a_m] = av.w;
            *(float4*)&Bs[p ^ 1][b_k][b_n] = bv;
        }
        __syncthreads();
        p ^= 1;
    }

#pragma unroll
    for (int i = 0; i < 8; i++) {
        int m = bm + ty * 4 + (i & 3) + (i & 4) * 16;
#pragma unroll
        for (int pr = 0; pr < 4; pr++) {
            float lo, hi;
            unpack2(acc2[i][pr], lo, hi);
            int n0 = bn + (pr & 2) * 32 + tx * 4 + (pr & 1) * 2;
            float v0 = lo + bias[n0];
            float v1 = hi + bias[n0 + 1];
            if (mode == 0) {
                C[(size_t)m * N + n0]     = v0;
                C[(size_t)m * N + n0 + 1] = v1;
            } else {
                int bb = m >> 11;
                int t  = m & (T - 1);
                int h0 = n0 >> 6;
                int d0 = n0 & (DK - 1);
                size_t base = (((size_t)(bb * NH + h0)) * T + t) * DK;
                C[base + d0]     = v0;
                C[base + d0 + 1] = v1;   // pair never crosses a head (64-aligned)
            }
        }
    }
}

// ---------------------------------------------------------------------------
// Flash attention: BQ=128 q-rows x BK=128 keys per tile, 256 threads.
// Micro-tile: score 8 rows x 8 cols (split-64 col map), PV 8 rows x 4 dcols.
// f32x2 packed FMA throughout.
// ---------------------------------------------------------------------------
#define BQ 128
#define BK 128
#define QST 132
#define VST 68
#define ATTN_SMEM ((2*64*QST + BK*VST + BQ*QST) * 4)

__global__ __launch_bounds__(256, 1) void attn_kernel(
    const float* __restrict__ Qh, const float* __restrict__ Kh,
    const float* __restrict__ Vh, const int* __restrict__ mask,
    float* __restrict__ Aout)
{
    extern __shared__ float sm[];
    float* Qt = sm;                      // [64 d][QST]  (transposed Q)
    float* Kt = Qt + 64 * QST;           // [64 d][QST]  (transposed K)
    float* Vs = Kt + 64 * QST;           // [BK c][VST]
    float* Ps = Vs + BK * VST;           // [BQ r][QST]
    __shared__ float Mk[BK];

    int tid = threadIdx.x;
    int tx = tid & 15;
    int ty = tid >> 4;
    int q0 = blockIdx.x * BQ;
    int h  = blockIdx.y;
    int b  = blockIdx.z;
    int bh = b * NH + h;

    const float* Qbase = Qh + ((size_t)bh * T + q0) * DK;
    const float* Kbase = Kh + (size_t)bh * T * DK;
    const float* Vbase = Vh + (size_t)bh * T * DK;

    // Load Q tile transposed
    for (int i = tid; i < BQ * 16; i += 256) {
        int r  = i >> 4;
        int d4 = (i & 15) * 4;
        float4 qv = *(const float4*)&Qbase[r * DK + d4];
        Qt[(d4 + 0) * QST + r] = qv.x;
        Qt[(d4 + 1) * QST + r] = qv.y;
        Qt[(d4 + 2) * QST + r] = qv.z;
        Qt[(d4 + 3) * QST + r] = qv.w;
    }

    float m_r[8], l_r[8];
    ull acc2[8][2];
#pragma unroll
    for (int i = 0; i < 8; i++) {
        m_r[i] = -1e30f;
        l_r[i] = 0.f;
        acc2[i][0] = 0ULL;
        acc2[i][1] = 0ULL;
    }

    const float scale = 0.125f;   // 1/sqrt(64)

    for (int k0 = 0; k0 < T; k0 += BK) {
        // Load K (transposed) and V tiles + mask
        for (int i = tid; i < BK * 16; i += 256) {
            int r  = i >> 4;
            int d4 = (i & 15) * 4;
            float4 kv = *(const float4*)&Kbase[(k0 + r) * DK + d4];
            Kt[(d4 + 0) * QST + r] = kv.x;
            Kt[(d4 + 1) * QST + r] = kv.y;
            Kt[(d4 + 2) * QST + r] = kv.z;
            Kt[(d4 + 3) * QST + r] = kv.w;
            float4 vv = *(const float4*)&Vbase[(k0 + r) * DK + d4];
            *(float4*)&Vs[r * VST + d4] = vv;
        }
        if (tid < BK)
            Mk[tid] = mask[b * T + k0 + tid] ? 0.f : -1e30f;
        __syncthreads();

        // Score phase: 8 rows (ty*8+i) x 8 cols (tx*4+{0..3}, 64+tx*4+{0..3})
        ull s2[8][4];
#pragma unroll
        for (int i = 0; i < 8; i++)
#pragma unroll
            for (int j = 0; j < 4; j++) s2[i][j] = 0ULL;

#pragma unroll 4
        for (int d = 0; d < DK; d++) {
            float a[8];
            *(float4*)&a[0] = *(const float4*)&Qt[d * QST + ty * 8];
            *(float4*)&a[4] = *(const float4*)&Qt[d * QST + ty * 8 + 4];
            ulonglong2 b01 = *(const ulonglong2*)&Kt[d * QST + tx * 4];
            ulonglong2 b23 = *(const ulonglong2*)&Kt[d * QST + 64 + tx * 4];
#pragma unroll
            for (int i = 0; i < 8; i++) {
                ull ad = dup2(a[i]);
                ffma2(s2[i][0], ad, b01.x);
                ffma2(s2[i][1], ad, b01.y);
                ffma2(s2[i][2], ad, b23.x);
                ffma2(s2[i][3], ad, b23.y);
            }
        }

        float mk[8];
#pragma unroll
        for (int j = 0; j < 4; j++) {
            mk[j]     = Mk[tx * 4 + j];
            mk[4 + j] = Mk[64 + tx * 4 + j];
        }

        // Online softmax (rows reduced across the 16 tx lanes)
#pragma unroll
        for (int i = 0; i < 8; i++) {
            float sc[8];
            unpack2(s2[i][0], sc[0], sc[1]);
            unpack2(s2[i][1], sc[2], sc[3]);
            unpack2(s2[i][2], sc[4], sc[5]);
            unpack2(s2[i][3], sc[6], sc[7]);
#pragma unroll
            for (int j = 0; j < 8; j++) sc[j] = sc[j] * scale + mk[j];

            float mx = sc[0];
#pragma unroll
            for (int j = 1; j < 8; j++) mx = fmaxf(mx, sc[j]);
#pragma unroll
            for (int msk = 8; msk >= 1; msk >>= 1)
                mx = fmaxf(mx, __shfl_xor_sync(0xffffffffu, mx, msk));
            float m_new = fmaxf(m_r[i], mx);

            float pj[8];
            float sum = 0.f;
#pragma unroll
            for (int j = 0; j < 8; j++) { pj[j] = __expf(sc[j] - m_new); sum += pj[j]; }
#pragma unroll
            for (int msk = 8; msk >= 1; msk >>= 1)
                sum += __shfl_xor_sync(0xffffffffu, sum, msk);

            float alpha = __expf(m_r[i] - m_new);
            l_r[i] = l_r[i] * alpha + sum;
            m_r[i] = m_new;
            ull am = dup2(alpha);
            acc2[i][0] = mul2(acc2[i][0], am);
            acc2[i][1] = mul2(acc2[i][1], am);

            int r = ty * 8 + i;
            *(float4*)&Ps[r * QST + tx * 4]      = make_float4(pj[0], pj[1], pj[2], pj[3]);
            *(float4*)&Ps[r * QST + 64 + tx * 4] = make_float4(pj[4], pj[5], pj[6], pj[7]);
        }
        __syncthreads();

        // PV phase: acc[8 rows][4 dcols = tx*4..tx*4+3]
#pragma unroll 2
        for (int c0 = 0; c0 < BK; c0 += 4) {
            ulonglong2 v0 = *(const ulonglong2*)&Vs[(c0 + 0) * VST + tx * 4];
            ulonglong2 v1 = *(const ulonglong2*)&Vs[(c0 + 1) * VST + tx * 4];
            ulonglong2 v2 = *(const ulonglong2*)&Vs[(c0 + 2) * VST + tx * 4];
            ulonglong2 v3 = *(const ulonglong2*)&Vs[(c0 + 3) * VST + tx * 4];
#pragma unroll
            for (int i = 0; i < 8; i++) {
                float4 pv = *(const float4*)&Ps[(ty * 8 + i) * QST + c0];
                ull pd;
                pd = dup2(pv.x); ffma2(acc2[i][0], pd, v0.x); ffma2(acc2[i][1], pd, v0.y);
                pd = dup2(pv.y); ffma2(acc2[i][0], pd, v1.x); ffma2(acc2[i][1], pd, v1.y);
                pd = dup2(pv.z); ffma2(acc2[i][0], pd, v2.x); ffma2(acc2[i][1], pd, v2.y);
                pd = dup2(pv.w); ffma2(acc2[i][0], pd, v3.x); ffma2(acc2[i][1], pd, v3.y);
            }
        }
        __syncthreads();
    }

    // Write A in [N*T, DM] layout
#pragma unroll
    for (int i = 0; i < 8; i++) {
        float inv = 1.f / l_r[i];
        float o0, o1, o2, o3;
        unpack2(acc2[i][0], o0, o1);
        unpack2(acc2[i][1], o2, o3);
        int t = q0 + ty * 8 + i;
        float4 o = make_float4(o0 * inv, o1 * inv, o2 * inv, o3 * inv);
        *(float4*)&Aout[((size_t)(b * T + t)) * DM + h * DK + tx * 4] = o;
    }
}

// ---------------------------------------------------------------------------
extern "C" void kernel_launch(void* const* d_in, const int* in_sizes, int n_in,
                              void* d_out, int out_size)
{
    const float* q   = (const float*)d_in[0];
    const float* k   = (const float*)d_in[1];
    const float* v   = (const float*)d_in[2];
    const int*   msk = (const int*)  d_in[3];
    const float* Wq  = (const float*)d_in[4];
    const float* bq  = (const float*)d_in[5];
    const float* Wk  = (const float*)d_in[6];
    const float* bk  = (const float*)d_in[7];
    const float* Wv  = (const float*)d_in[8];
    const float* bv  = (const float*)d_in[9];
    const float* Wo  = (const float*)d_in[10];
    const float* bo  = (const float*)d_in[11];
    float* out = (float*)d_out;

    float* Qh;   cudaGetSymbolAddress((void**)&Qh, g_Qh);
    float* Kh;   cudaGetSymbolAddress((void**)&Kh, g_Kh);
    float* Vh;   cudaGetSymbolAddress((void**)&Vh, g_Vh);
    float* Abuf; cudaGetSymbolAddress((void**)&Abuf, g_A);

    cudaFuncSetAttribute(attn_kernel,
                         cudaFuncAttributeMaxDynamicSharedMemorySize, ATTN_SMEM);

    dim3 gg(DM / 128, NT / 128);   // (8, 32)
    gemm_kernel<<<gg, 256>>>(q, Wq, bq, Qh, NT, DM, DM, 1);
    gemm_kernel<<<gg, 256>>>(k, Wk, bk, Kh, NT, DM, DM, 1);
    gemm_kernel<<<gg, 256>>>(v, Wv, bv, Vh, NT, DM, DM, 1);

    dim3 ga(T / BQ, NH, NB);       // (16, 16, 2)
    attn_kernel<<<ga, 256, ATTN_SMEM>>>(Qh, Kh, Vh, msk, Abuf);

    gemm_kernel<<<gg, 256>>>(Abuf, Wo, bo, out, NT, DM, DM, 0);
}